// round 4
// baseline (speedup 1.0000x reference)
#include <cuda_runtime.h>

#define BATCH 2
#define NN 1024
#define CC 64
#define ROWS (BATCH * NN)   // 2048

// yhat = sqrt(2*log2e) * (X@W); R = 0.5*||yhat||^2 = log2e*||y||^2
// => t = <yhat_i,yhat_j> - R_i - R_j = -log2e * q;  adj = 2^t.
#define SCALE_Y 1.6983709f

__device__ float g_Yt[CC * ROWS];   // [d][row]
__device__ float g_R[ROWS];

// ---------------------------------------------------------------------------
// Kernel A: Y = scale * X @ W, transposed store + row norms.
// 256 blocks x 128 threads; 8 rows per block (2 rows per warp).
// ---------------------------------------------------------------------------
__global__ void y_kernel(const float* __restrict__ X, const float* __restrict__ W) {
    __shared__ float Ws[64 * 64];   // [c][d]
    __shared__ float Xs[8 * 64];
    __shared__ float Ys[64 * 9];    // transposed staging, odd stride
    const int tid = threadIdx.x;
    const int rowBase = blockIdx.x * 8;

    #pragma unroll
    for (int i = tid; i < 64 * 64; i += 128) Ws[i] = W[i];
    for (int i = tid; i < 8 * 64; i += 128) Xs[i] = X[rowBase * 64 + i];
    __syncthreads();

    const int warp = tid >> 5, lane = tid & 31;
    #pragma unroll
    for (int r2 = 0; r2 < 2; r2++) {
        const int row = warp * 2 + r2;
        float a0 = 0.f, a1 = 0.f;
        #pragma unroll
        for (int c0 = 0; c0 < 64; c0++) {
            const float xv = Xs[row * 64 + c0];
            a0 = fmaf(xv, Ws[c0 * 64 + lane],      a0);
            a1 = fmaf(xv, Ws[c0 * 64 + lane + 32], a1);
        }
        a0 *= SCALE_Y; a1 *= SCALE_Y;
        Ys[lane * 9 + row]        = a0;
        Ys[(lane + 32) * 9 + row] = a1;
        float s = a0 * a0 + a1 * a1;
        #pragma unroll
        for (int o = 16; o; o >>= 1) s += __shfl_xor_sync(0xffffffffu, s, o);
        if (lane == 0) g_R[rowBase + row] = 0.5f * s;
    }
    __syncthreads();
    for (int idx = tid; idx < 64 * 8; idx += 128) {   // coalesced-by-block store
        const int d = idx >> 3, r = idx & 7;
        g_Yt[d * ROWS + rowBase + r] = Ys[d * 9 + r];
    }
}

// ---------------------------------------------------------------------------
// Kernel B: 64(i) x 32(j) tile per block, 128 threads, 4x4 per thread.
// blockIdx.x in [0, 272): ti = largest with ti^2+ti <= t, tj = t - ti^2 - ti,
// tj in [0, 2ti+2). Tiles with tj < 2ti are strictly sub-diagonal:
// compute + mirror. Boundary tiles (tj = 2ti, 2ti+1) tile the diagonal
// square exactly once: compute, no mirror (race-free, deterministic).
// ---------------------------------------------------------------------------
__global__ void adj_kernel(float* __restrict__ out) {
    __shared__ float Yi[64 * 64];   // [d][64 i-rows]
    __shared__ float Yj[64 * 32];   // [d][32 j-rows]
    __shared__ float Ri[64], Rj[32];

    const int t = blockIdx.x, b = blockIdx.y;
    int ti = (int)((sqrtf(4.0f * (float)t + 1.0f) - 1.0f) * 0.5f);
    while ((ti + 1) * (ti + 2) <= t) ti++;
    while (ti * (ti + 1) > t) ti--;
    const int tj = t - ti * (ti + 1);

    const int tid = threadIdx.x;
    const int gi = b * NN + ti * 64;
    const int gj = b * NN + tj * 32;

    #pragma unroll
    for (int idx = tid; idx < 4096; idx += 128) {
        const int d = idx >> 6, r = idx & 63;
        Yi[idx] = g_Yt[d * ROWS + gi + r];
    }
    #pragma unroll
    for (int idx = tid; idx < 2048; idx += 128) {
        const int d = idx >> 5, r = idx & 31;
        Yj[idx] = g_Yt[d * ROWS + gj + r];
    }
    if (tid < 64)       Ri[tid]      = g_R[gi + tid];
    else if (tid < 96)  Rj[tid - 64] = g_R[gj + (tid - 64)];
    __syncthreads();

    const int tx = tid & 7;    // j: 4 cols
    const int ty = tid >> 3;   // i: 4 rows

    float acc[4][4];
    #pragma unroll
    for (int l = 0; l < 4; l++)
        #pragma unroll
        for (int k = 0; k < 4; k++) acc[l][k] = 0.f;

    #pragma unroll 8
    for (int d = 0; d < 64; d++) {
        const float4 av4 = *(const float4*)&Yi[d * 64 + ty * 4];
        const float4 bv4 = *(const float4*)&Yj[d * 32 + tx * 4];
        const float av[4] = {av4.x, av4.y, av4.z, av4.w};
        const float bb[4] = {bv4.x, bv4.y, bv4.z, bv4.w};
        #pragma unroll
        for (int l = 0; l < 4; l++)
            #pragma unroll
            for (int k = 0; k < 4; k++)
                acc[l][k] = fmaf(av[l], bb[k], acc[l][k]);
    }

    float Rli[4], Rlj[4];
    #pragma unroll
    for (int l = 0; l < 4; l++) Rli[l] = Ri[ty * 4 + l];
    #pragma unroll
    for (int k = 0; k < 4; k++) Rlj[k] = Rj[tx * 4 + k];

    // MUFU-free 2^t with round-to-nearest split + degree-6 poly, FTZ.
    const float MAGIC = 12582912.0f;   // 2^23 + 2^22
    const int   MAGIC_I = 0x4B400000;
    const int iBase = ti * 64 + ty * 4;       // global row base of this thread
    const int jBase = tj * 32 + tx * 4;       // global col base
    #pragma unroll
    for (int l = 0; l < 4; l++) {
        #pragma unroll
        for (int k = 0; k < 4; k++) {
            float tt = (acc[l][k] - Rli[l]) - Rlj[k];
            float sh = tt + MAGIC;
            float rn = sh - MAGIC;
            float f  = tt - rn;
            int   n  = __float_as_int(sh) - MAGIC_I;
            float p = 1.5403530e-4f;
            p = fmaf(p, f, 1.3333558e-3f);
            p = fmaf(p, f, 9.6181291e-3f);
            p = fmaf(p, f, 5.5504109e-2f);
            p = fmaf(p, f, 2.4022651e-1f);
            p = fmaf(p, f, 6.9314718e-1f);
            p = fmaf(p, f, 1.0f);
            float sc = __int_as_float((n + 127) << 23);
            float e  = (n < -126) ? 0.0f : p * sc;
            if ((iBase + l) == (jBase + k)) e += 1.0f;
            acc[l][k] = e;
        }
    }

    const size_t outBase = (size_t)b * (size_t)NN * (size_t)NN;

    // Primary write: float4 per row (8 tx cover 128B per row).
    #pragma unroll
    for (int l = 0; l < 4; l++) {
        *(float4*)&out[outBase + (size_t)(iBase + l) * NN + jBase] =
            make_float4(acc[l][0], acc[l][1], acc[l][2], acc[l][3]);
    }

    // Mirror only for strictly sub-diagonal tiles.
    if (tj < 2 * ti) {
        #pragma unroll
        for (int k = 0; k < 4; k++) {
            *(float4*)&out[outBase + (size_t)(jBase + k) * NN + iBase] =
                make_float4(acc[0][k], acc[1][k], acc[2][k], acc[3][k]);
        }
    }
}

// ---------------------------------------------------------------------------
extern "C" void kernel_launch(void* const* d_in, const int* in_sizes, int n_in,
                              void* d_out, int out_size) {
    const float* X = (const float*)d_in[0];   // (2,1024,64)
    const float* W = (const float*)d_in[1];   // (64,64)
    float* out = (float*)d_out;               // (2,1024,1024)

    y_kernel<<<256, 128>>>(X, W);
    adj_kernel<<<dim3(272, 2), 128>>>(out);
    (void)in_sizes; (void)n_in; (void)out_size;
}